// round 2
// baseline (speedup 1.0000x reference)
#include <cuda_runtime.h>

// Problem constants (fixed by the dataset)
#define BH   32      // b*h = 2*16
#define LSEQ 4096
#define DK   16
#define DV   64
#define CS   256     // chunk size
#define NC   16      // L / CS

// Per-(head,chunk) state layout in scratch:
//   kvq  [256][64]  (de-major outer-product state)    16384 floats
//   kvl  [16][64]                                      1024 floats
//   kksum[256]                                          256 floats
//   ksum [16]                                            16 floats
//   vsum [64]                                            64 floats
#define ST_STRIDE 17792
#define OFF_KVQ 0
#define OFF_KVL 16384
#define OFF_KK  17408
#define OFF_KS  17664
#define OFF_VS  17680
#define ST_TOTAL 17744

__device__ float g_state[(size_t)BH * NC * ST_STRIDE];

// ---------------------------------------------------------------------------
// Kernel 1: per-chunk state sums.
// grid (BH, NC), 256 threads, dyn smem = 256*17 + 256*64 floats
// ---------------------------------------------------------------------------
__global__ __launch_bounds__(256, 1)
void k_build(const float* __restrict__ kin, const float* __restrict__ vin) {
    const int head = blockIdx.x, ch = blockIdx.y;
    extern __shared__ float sm[];
    float* sk = sm;                 // [256][17] padded
    float* sv = sm + CS * 17;       // [256][64]
    const float* kg = kin + ((size_t)head * LSEQ + (size_t)ch * CS) * DK;
    const float* vg = vin + ((size_t)head * LSEQ + (size_t)ch * CS) * DV;
    const int tid = threadIdx.x;

    for (int i = tid; i < CS * DK; i += 256)
        sk[(i >> 4) * 17 + (i & 15)] = kg[i];
    {
        const float4* s4 = (const float4*)vg;
        float4* d4 = (float4*)sv;
        #pragma unroll 4
        for (int i = tid; i < CS * DV / 4; i += 256) d4[i] = s4[i];
    }
    __syncthreads();

    float* st = g_state + (size_t)(head * NC + ch) * ST_STRIDE;
    const int ty = tid >> 3, tx = tid & 7;
    const int d0 = ty >> 1, e0 = (ty & 1) * 8;   // de = ty*8+j maps to (d0, e0+j)

    // kvq[de][f] = sum_c k_d * k_e * v_f  — GEMM M=256(de) N=64(f) K=256(c)
    float acc[8][8];
    #pragma unroll
    for (int j = 0; j < 8; j++)
        #pragma unroll
        for (int i = 0; i < 8; i++) acc[j][i] = 0.f;

    #pragma unroll 2
    for (int cc = 0; cc < CS; cc++) {
        const float* kr = sk + cc * 17;
        float kd = kr[d0];
        float a[8];
        #pragma unroll
        for (int j = 0; j < 8; j++) a[j] = kd * kr[e0 + j];
        float4 b0 = *(const float4*)(sv + cc * 64 + tx * 8);
        float4 b1 = *(const float4*)(sv + cc * 64 + tx * 8 + 4);
        float b[8] = {b0.x, b0.y, b0.z, b0.w, b1.x, b1.y, b1.z, b1.w};
        #pragma unroll
        for (int j = 0; j < 8; j++)
            #pragma unroll
            for (int i = 0; i < 8; i++) acc[j][i] += a[j] * b[i];
    }
    #pragma unroll
    for (int j = 0; j < 8; j++) {
        float* dst = st + OFF_KVQ + (ty * 8 + j) * 64 + tx * 8;
        *(float4*)dst       = make_float4(acc[j][0], acc[j][1], acc[j][2], acc[j][3]);
        *(float4*)(dst + 4) = make_float4(acc[j][4], acc[j][5], acc[j][6], acc[j][7]);
    }

    // kvl[d][f] = sum_c k_d v_f : thread -> (d = tid>>4, 4 f's)
    {
        int dd = tid >> 4, fb = (tid & 15) * 4;
        float s0 = 0, s1 = 0, s2 = 0, s3 = 0;
        #pragma unroll 4
        for (int cc = 0; cc < CS; cc++) {
            float kd = sk[cc * 17 + dd];
            float4 vv = *(const float4*)(sv + cc * 64 + fb);
            s0 += kd * vv.x; s1 += kd * vv.y; s2 += kd * vv.z; s3 += kd * vv.w;
        }
        *(float4*)(st + OFF_KVL + dd * 64 + fb) = make_float4(s0, s1, s2, s3);
    }
    // kksum[de]
    {
        int dd = tid >> 4, ee = tid & 15;
        float s = 0;
        #pragma unroll 4
        for (int cc = 0; cc < CS; cc++) s += sk[cc * 17 + dd] * sk[cc * 17 + ee];
        st[OFF_KK + tid] = s;
    }
    if (tid < DK) {
        float s = 0;
        #pragma unroll 4
        for (int cc = 0; cc < CS; cc++) s += sk[cc * 17 + tid];
        st[OFF_KS + tid] = s;
    }
    if (tid < DV) {
        float s = 0;
        #pragma unroll 4
        for (int cc = 0; cc < CS; cc++) s += sv[cc * 64 + tid];
        st[OFF_VS + tid] = s;
    }
}

// ---------------------------------------------------------------------------
// Kernel 2: exclusive prefix scan over the chunk axis, per head.
// grid (BH, 8), 256 threads
// ---------------------------------------------------------------------------
__global__ void k_scan() {
    const int head = blockIdx.x;
    float* base = g_state + (size_t)head * NC * ST_STRIDE;
    for (int i = blockIdx.y * blockDim.x + threadIdx.x; i < ST_TOTAL;
         i += gridDim.y * blockDim.x) {
        float run = 0.f;
        #pragma unroll
        for (int c = 0; c < NC; c++) {
            float t = base[(size_t)c * ST_STRIDE + i];
            base[(size_t)c * ST_STRIDE + i] = run;
            run += t;
        }
    }
}

// ---------------------------------------------------------------------------
// GEMM block: acc[8][8] += A[256xKB] @ B[KBx64], A padded stride 65.
// ---------------------------------------------------------------------------
template <int KB>
__device__ __forceinline__ void gemm_block(const float* __restrict__ sA,
                                           const float* __restrict__ sB,
                                           int ty, int tx, float acc[8][8]) {
    #pragma unroll 2
    for (int kk = 0; kk < KB; kk++) {
        float a[8];
        #pragma unroll
        for (int j = 0; j < 8; j++) a[j] = sA[(ty * 8 + j) * 65 + kk];
        float4 b0 = *(const float4*)(sB + kk * 64 + tx * 8);
        float4 b1 = *(const float4*)(sB + kk * 64 + tx * 8 + 4);
        float b[8] = {b0.x, b0.y, b0.z, b0.w, b1.x, b1.y, b1.z, b1.w};
        #pragma unroll
        for (int j = 0; j < 8; j++)
            #pragma unroll
            for (int i = 0; i < 8; i++) acc[j][i] += a[j] * b[i];
    }
}

// ---------------------------------------------------------------------------
// Kernel 3: per-(head,chunk) output.
// O = mask(1+S+0.5S^2) @ V  +  0.5*Q2 @ KVq_prev  +  Q @ KVl_prev + vsum_prev
// z = rowsums of the same A-blocks against {1, kksum, ksum} + ch*CS (+ local)
// grid (BH, NC), 256 threads
// ---------------------------------------------------------------------------
__global__ __launch_bounds__(256, 1)
void k_main(const float* __restrict__ qin, const float* __restrict__ kin,
            const float* __restrict__ vin, float* __restrict__ out) {
    const int head = blockIdx.x, ch = blockIdx.y;
    extern __shared__ float sm[];
    float* sq  = sm;                  // [256][17]
    float* sk  = sq + CS * 17;        // [256][17]
    float* sA  = sk + CS * 17;        // [256][65]
    float* sB  = sA + CS * 65;        // [64][64]
    float* skk = sB + 64 * 64;        // [256]
    float* sks = skk + 256;           // [16]
    float* szs = sks + 16;            // [256]

    const float* qg = qin + ((size_t)head * LSEQ + (size_t)ch * CS) * DK;
    const float* kg = kin + ((size_t)head * LSEQ + (size_t)ch * CS) * DK;
    const float* vg = vin + ((size_t)head * LSEQ + (size_t)ch * CS) * DV;
    const float* st = g_state + (size_t)(head * NC + ch) * ST_STRIDE;
    const int tid = threadIdx.x, ty = tid >> 3, tx = tid & 7;

    for (int i = tid; i < CS * DK; i += 256) {
        int r = i >> 4, cc = i & 15;
        sq[r * 17 + cc] = qg[i] * 0.25f;   // q * d^-0.5
        sk[r * 17 + cc] = kg[i];
    }
    skk[tid] = st[OFF_KK + tid];
    if (tid < DK) sks[tid] = st[OFF_KS + tid];
    __syncthreads();

    float acc[8][8];
    #pragma unroll
    for (int j = 0; j < 8; j++)
        #pragma unroll
        for (int i = 0; i < 8; i++) acc[j][i] = 0.f;
    float zacc = 0.f;

    // ---- 4 intra-chunk blocks: A = mask(1 + S + 0.5 S^2), B = V block ----
    for (int jb = 0; jb < 4; jb++) {
        {
            const float4* s4 = (const float4*)(vg + jb * 64 * DV);
            float4* d4 = (float4*)sB;
            #pragma unroll 4
            for (int i = tid; i < 64 * DV / 4; i += 256) d4[i] = s4[i];
        }
        const int colb = jb * 64 + tx * 8;
        #pragma unroll
        for (int jp = 0; jp < 4; jp++) {
            int r0 = ty * 8 + jp * 2;
            float s0[8], s1[8];
            #pragma unroll
            for (int i = 0; i < 8; i++) { s0[i] = 0.f; s1[i] = 0.f; }
            #pragma unroll
            for (int dd = 0; dd < DK; dd++) {
                float q0 = sq[r0 * 17 + dd];
                float q1 = sq[(r0 + 1) * 17 + dd];
                #pragma unroll
                for (int i = 0; i < 8; i++) {
                    float kv = sk[(colb + i) * 17 + dd];
                    s0[i] += q0 * kv;
                    s1[i] += q1 * kv;
                }
            }
            #pragma unroll
            for (int i = 0; i < 8; i++) {
                int col = colb + i;
                sA[r0 * 65 + tx * 8 + i] =
                    (r0 >= col) ? 1.f + s0[i] + 0.5f * s0[i] * s0[i] : 0.f;
                sA[(r0 + 1) * 65 + tx * 8 + i] =
                    (r0 + 1 >= col) ? 1.f + s1[i] + 0.5f * s1[i] * s1[i] : 0.f;
            }
        }
        __syncthreads();
        gemm_block<64>(sA, sB, ty, tx, acc);
        {
            const float* ar = sA + tid * 65;
            float zs = 0.f;
            #pragma unroll 4
            for (int kk = 0; kk < 64; kk++) zs += ar[kk];
            zacc += zs;
        }
        __syncthreads();
    }

    // ---- 4 quadratic inter blocks: A = 0.5*q_d*q_e, B = KVq_prev rows ----
    for (int qb = 0; qb < 4; qb++) {
        {
            const float4* s4 = (const float4*)(st + OFF_KVQ + qb * 64 * 64);
            float4* d4 = (float4*)sB;
            #pragma unroll 4
            for (int i = tid; i < 64 * 64 / 4; i += 256) d4[i] = s4[i];
        }
        const int debase = qb * 64 + tx * 8;
        const int dd = debase >> 4;
        const int eb = debase & 15;
        #pragma unroll
        for (int j = 0; j < 8; j++) {
            int r = ty * 8 + j;
            float qd = 0.5f * sq[r * 17 + dd];
            #pragma unroll
            for (int i = 0; i < 8; i++)
                sA[r * 65 + tx * 8 + i] = qd * sq[r * 17 + eb + i];
        }
        __syncthreads();
        gemm_block<64>(sA, sB, ty, tx, acc);
        {
            const float* ar = sA + tid * 65;
            const float* wk = skk + qb * 64;
            float zs = 0.f;
            #pragma unroll 4
            for (int kk = 0; kk < 64; kk++) zs += ar[kk] * wk[kk];
            zacc += zs;
        }
        __syncthreads();
    }

    // ---- linear inter block: A = Q (scaled), B = KVl_prev [16][64] ----
    {
        {
            const float4* s4 = (const float4*)(st + OFF_KVL);
            float4* d4 = (float4*)sB;
            d4[tid] = s4[tid];   // 1024 floats = 256 float4
        }
        for (int i = tid; i < CS * DK; i += 256) {
            int r = i >> 4, cc = i & 15;
            sA[r * 65 + cc] = sq[r * 17 + cc];
        }
        __syncthreads();
        gemm_block<16>(sA, sB, ty, tx, acc);
        {
            const float* ar = sA + tid * 65;
            float zs = 0.f;
            #pragma unroll
            for (int kk = 0; kk < 16; kk++) zs += ar[kk] * sks[kk];
            zacc += zs;
        }
    }

    // z: intra masked A already contributed (local l+1); add prior-count
    zacc += (float)(ch * CS);
    szs[tid] = zacc;
    __syncthreads();

    float vsr[8];
    #pragma unroll
    for (int i = 0; i < 8; i++) vsr[i] = st[OFF_VS + tx * 8 + i];
    float* og = out + ((size_t)head * LSEQ + (size_t)ch * CS) * DV;
    #pragma unroll
    for (int j = 0; j < 8; j++) {
        int r = ty * 8 + j;
        float inv = 1.f / (szs[r] + 1e-6f);
        float4 o0 = make_float4((acc[j][0] + vsr[0]) * inv, (acc[j][1] + vsr[1]) * inv,
                                (acc[j][2] + vsr[2]) * inv, (acc[j][3] + vsr[3]) * inv);
        float4 o1 = make_float4((acc[j][4] + vsr[4]) * inv, (acc[j][5] + vsr[5]) * inv,
                                (acc[j][6] + vsr[6]) * inv, (acc[j][7] + vsr[7]) * inv);
        *(float4*)(og + r * DV + tx * 8)     = o0;
        *(float4*)(og + r * DV + tx * 8 + 4) = o1;
    }
}

// ---------------------------------------------------------------------------
extern "C" void kernel_launch(void* const* d_in, const int* in_sizes, int n_in,
                              void* d_out, int out_size) {
    const float* q = (const float*)d_in[0];
    const float* k = (const float*)d_in[1];
    const float* v = (const float*)d_in[2];
    float* out = (float*)d_out;

    const int smem1 = (CS * 17 + CS * DV) * (int)sizeof(float);
    const int smem3 = (CS * 17 * 2 + CS * 65 + 64 * 64 + 256 + 16 + 256) * (int)sizeof(float);

    cudaFuncSetAttribute(k_build, cudaFuncAttributeMaxDynamicSharedMemorySize, smem1);
    cudaFuncSetAttribute(k_main,  cudaFuncAttributeMaxDynamicSharedMemorySize, smem3);

    k_build<<<dim3(BH, NC), 256, smem1>>>(k, v);
    k_scan<<<dim3(BH, 8), 256>>>();
    k_main<<<dim3(BH, NC), 256, smem3>>>(q, k, v, out);
}

// round 3
// speedup vs baseline: 1.8030x; 1.8030x over previous
#include <cuda_runtime.h>
#include <cstdint>

#define BH   32
#define LSEQ 4096
#define DK   16
#define DV   64
#define CS   256
#define NC   16

#define ST_STRIDE 17792
#define OFF_KVQ 0
#define OFF_KVL 16384
#define OFF_KK  17408
#define OFF_KS  17664
#define OFF_VS  17680
#define ST_TOTAL 17744

__device__ float g_state[(size_t)BH * NC * ST_STRIDE];

// float -> tf32 bits (valid fp32 bit pattern with truncated mantissa)
__device__ __forceinline__ unsigned f2t(float x) {
    unsigned u;
    asm("cvt.rna.tf32.f32 %0, %1;" : "=r"(u) : "f"(x));
    return u;
}

__device__ __forceinline__ void mma8(float* c, unsigned a0, unsigned a1,
                                     unsigned a2, unsigned a3,
                                     unsigned b0, unsigned b1) {
    asm volatile(
        "mma.sync.aligned.m16n8k8.row.col.f32.tf32.tf32.f32 "
        "{%0,%1,%2,%3},{%4,%5,%6,%7},{%8,%9},{%0,%1,%2,%3};"
        : "+f"(c[0]), "+f"(c[1]), "+f"(c[2]), "+f"(c[3])
        : "r"(a0), "r"(a1), "r"(a2), "r"(a3), "r"(b0), "r"(b1));
}

// One K=64 tile: C[256x64] += A[256x64](sAu, stride 68) @ B[64x64](sBu, stride 72)
__device__ __forceinline__ void gemm_tile(const unsigned* __restrict__ sAu,
                                          const unsigned* __restrict__ sBu,
                                          int wm, int wn, int g, int tg,
                                          float c[4][4][4]) {
    #pragma unroll
    for (int ks = 0; ks < 8; ks++) {
        unsigned a[4][4];
        #pragma unroll
        for (int mt = 0; mt < 4; mt++) {
            int rr = 64 * wm + 16 * mt + g;
            a[mt][0] = sAu[rr * 68 + 8 * ks + tg];
            a[mt][1] = sAu[(rr + 8) * 68 + 8 * ks + tg];
            a[mt][2] = sAu[rr * 68 + 8 * ks + tg + 4];
            a[mt][3] = sAu[(rr + 8) * 68 + 8 * ks + tg + 4];
        }
        unsigned b[4][2];
        #pragma unroll
        for (int nt = 0; nt < 4; nt++) {
            int fc = 32 * wn + 8 * nt + g;
            b[nt][0] = sBu[(8 * ks + tg) * 72 + fc];
            b[nt][1] = sBu[(8 * ks + tg + 4) * 72 + fc];
        }
        #pragma unroll
        for (int mt = 0; mt < 4; mt++)
            #pragma unroll
            for (int nt = 0; nt < 4; nt++)
                mma8(c[mt][nt], a[mt][0], a[mt][1], a[mt][2], a[mt][3],
                     b[nt][0], b[nt][1]);
    }
}

// ---------------------------------------------------------------------------
// Kernel 1: per-chunk state build. kvq via tf32 mma; small sums via FFMA.
// ---------------------------------------------------------------------------
__global__ __launch_bounds__(256, 1)
void k_build(const float* __restrict__ kin, const float* __restrict__ vin) {
    const int head = blockIdx.x, ch = blockIdx.y;
    extern __shared__ float sm[];
    float* sk = sm;                 // [256][17] fp32
    float* sA = sk + CS * 17;       // [256][68] tf32 bits
    float* sB = sA + 256 * 68;      // [64][72]  tf32 bits
    unsigned* sAu = (unsigned*)sA;
    unsigned* sBu = (unsigned*)sB;

    const float* kg = kin + ((size_t)head * LSEQ + (size_t)ch * CS) * DK;
    const float* vg = vin + ((size_t)head * LSEQ + (size_t)ch * CS) * DV;
    float* st = g_state + (size_t)(head * NC + ch) * ST_STRIDE;

    const int tid = threadIdx.x, warp = tid >> 5, lane = tid & 31;
    const int wm = warp >> 1, wn = warp & 1, g = lane >> 2, tg = lane & 3;

    for (int i = tid; i < CS * DK; i += 256)
        sk[(i >> 4) * 17 + (i & 15)] = kg[i];
    __syncthreads();

    float c[4][4][4];
    #pragma unroll
    for (int mt = 0; mt < 4; mt++)
        #pragma unroll
        for (int nt = 0; nt < 4; nt++)
            #pragma unroll
            for (int u = 0; u < 4; u++) c[mt][nt][u] = 0.f;

    const int kd_d = tid >> 4, kd_f = (tid & 15) * 4;
    float kvl[4] = {0.f, 0.f, 0.f, 0.f};
    float vsm = 0.f;

    for (int t = 0; t < 4; t++) {
        // stage V tile (tf32), float4 gmem loads
        for (int i = tid; i < 1024; i += 256) {
            int cc = i >> 4, f4 = (i & 15) * 4;
            float4 v = *(const float4*)&vg[(t * 64 + cc) * 64 + f4];
            *(uint4*)&sBu[cc * 72 + f4] =
                make_uint4(f2t(v.x), f2t(v.y), f2t(v.z), f2t(v.w));
        }
        // build A slice: rows (warp's 64 de-rows), cols 32*wn..32*wn+31
        #pragma unroll
        for (int rr = 0; rr < 2; rr++) {
            int r = 64 * wm + lane + 32 * rr;
            int d = r >> 4, e = r & 15;
            #pragma unroll
            for (int c4 = 0; c4 < 8; c4++) {
                unsigned pk[4];
                #pragma unroll
                for (int u = 0; u < 4; u++) {
                    int cc = t * 64 + 32 * wn + c4 * 4 + u;
                    pk[u] = f2t(sk[cc * 17 + d] * sk[cc * 17 + e]);
                }
                *(uint4*)&sAu[r * 68 + 32 * wn + c4 * 4] =
                    make_uint4(pk[0], pk[1], pk[2], pk[3]);
            }
        }
        __syncthreads();
        gemm_tile(sAu, sBu, wm, wn, g, tg, c);
        // kvl/vsum partials from tf32 V tile (tf32 bits are valid floats)
        #pragma unroll 4
        for (int cc = 0; cc < 64; cc++) {
            float kdv = sk[(t * 64 + cc) * 17 + kd_d];
            float4 vv = *(const float4*)&sB[cc * 72 + kd_f];
            kvl[0] += kdv * vv.x; kvl[1] += kdv * vv.y;
            kvl[2] += kdv * vv.z; kvl[3] += kdv * vv.w;
        }
        if (tid < 64) {
            #pragma unroll 4
            for (int cc = 0; cc < 64; cc++) vsm += sB[cc * 72 + tid];
        }
        __syncthreads();
    }

    // write kvq (fp32 accumulators)
    #pragma unroll
    for (int mt = 0; mt < 4; mt++)
        #pragma unroll
        for (int nt = 0; nt < 4; nt++) {
            int r0 = 64 * wm + 16 * mt + g, f = 32 * wn + 8 * nt + 2 * tg;
            *(float2*)&st[OFF_KVQ + r0 * 64 + f] =
                make_float2(c[mt][nt][0], c[mt][nt][1]);
            *(float2*)&st[OFF_KVQ + (r0 + 8) * 64 + f] =
                make_float2(c[mt][nt][2], c[mt][nt][3]);
        }
    *(float4*)&st[OFF_KVL + kd_d * 64 + kd_f] =
        make_float4(kvl[0], kvl[1], kvl[2], kvl[3]);
    {
        int d = tid >> 4, e = tid & 15;
        float s = 0.f;
        #pragma unroll 4
        for (int cc = 0; cc < CS; cc++) s += sk[cc * 17 + d] * sk[cc * 17 + e];
        st[OFF_KK + tid] = s;
    }
    if (tid < DK) {
        float s = 0.f;
        #pragma unroll 4
        for (int cc = 0; cc < CS; cc++) s += sk[cc * 17 + tid];
        st[OFF_KS + tid] = s;
    }
    if (tid < DV) st[OFF_VS + tid] = vsm;
}

// ---------------------------------------------------------------------------
// Kernel 2: exclusive prefix scan over chunk axis.
// ---------------------------------------------------------------------------
__global__ void k_scan() {
    const int head = blockIdx.x;
    float* base = g_state + (size_t)head * NC * ST_STRIDE;
    for (int i = blockIdx.y * blockDim.x + threadIdx.x; i < ST_TOTAL;
         i += gridDim.y * blockDim.x) {
        float run = 0.f;
        #pragma unroll
        for (int c = 0; c < NC; c++) {
            float t = base[(size_t)c * ST_STRIDE + i];
            base[(size_t)c * ST_STRIDE + i] = run;
            run += t;
        }
    }
}

// ---------------------------------------------------------------------------
// Kernel 3: per-(head,chunk) output via tf32 mma.
// ---------------------------------------------------------------------------
__global__ __launch_bounds__(256, 1)
void k_main(const float* __restrict__ qin, const float* __restrict__ kin,
            const float* __restrict__ vin, float* __restrict__ out) {
    const int head = blockIdx.x, ch = blockIdx.y;
    extern __shared__ float sm[];
    float* sq  = sm;                 // [256][17] fp32 (scaled q)
    float* sk  = sq + CS * 17;       // [256][17] fp32
    float* sA  = sk + CS * 17;       // [256][68] tf32 bits
    float* sB  = sA + 256 * 68;      // [64][72]  tf32 bits
    float* skk = sB + 64 * 72;       // [256]
    float* sks = skk + 256;          // [16]
    float* szs = sks + 16;           // [256]
    unsigned* sAu = (unsigned*)sA;
    unsigned* sBu = (unsigned*)sB;

    const float* qg = qin + ((size_t)head * LSEQ + (size_t)ch * CS) * DK;
    const float* kg = kin + ((size_t)head * LSEQ + (size_t)ch * CS) * DK;
    const float* vg = vin + ((size_t)head * LSEQ + (size_t)ch * CS) * DV;
    const float* st = g_state + (size_t)(head * NC + ch) * ST_STRIDE;

    const int tid = threadIdx.x, warp = tid >> 5, lane = tid & 31;
    const int wm = warp >> 1, wn = warp & 1, g = lane >> 2, tg = lane & 3;

    for (int i = tid; i < CS * DK; i += 256) {
        int r = i >> 4, cc = i & 15;
        sq[r * 17 + cc] = qg[i] * 0.25f;   // q * d^-0.5
        sk[r * 17 + cc] = kg[i];
    }
    skk[tid] = st[OFF_KK + tid];
    if (tid < DK) sks[tid] = st[OFF_KS + tid];
    szs[tid] = (float)(ch * CS);          // prior-chunk "count" term of z
    __syncthreads();

    // preload Q fragments (used for S-mma and the linear term)
    unsigned qf[4][2][4];
    #pragma unroll
    for (int mt = 0; mt < 4; mt++)
        #pragma unroll
        for (int ks = 0; ks < 2; ks++) {
            int r0 = 64 * wm + 16 * mt + g;
            qf[mt][ks][0] = f2t(sq[r0 * 17 + 8 * ks + tg]);
            qf[mt][ks][1] = f2t(sq[(r0 + 8) * 17 + 8 * ks + tg]);
            qf[mt][ks][2] = f2t(sq[r0 * 17 + 8 * ks + tg + 4]);
            qf[mt][ks][3] = f2t(sq[(r0 + 8) * 17 + 8 * ks + tg + 4]);
        }

    float c[4][4][4];
    #pragma unroll
    for (int mt = 0; mt < 4; mt++)
        #pragma unroll
        for (int nt = 0; nt < 4; nt++)
            #pragma unroll
            for (int u = 0; u < 4; u++) c[mt][nt][u] = 0.f;

    // ---- intra-chunk: A = mask(1 + S + 0.5 S^2), B = V tile ----
    for (int jb = 0; jb < 4; jb++) {
        for (int i = tid; i < 1024; i += 256) {
            int cc = i >> 4, f4 = (i & 15) * 4;
            float4 v = *(const float4*)&vg[(jb * 64 + cc) * 64 + f4];
            *(uint4*)&sBu[cc * 72 + f4] =
                make_uint4(f2t(v.x), f2t(v.y), f2t(v.z), f2t(v.w));
        }
        if (wm >= jb) {
            float zp[4][2];
            #pragma unroll
            for (int mt = 0; mt < 4; mt++) { zp[mt][0] = 0.f; zp[mt][1] = 0.f; }
            #pragma unroll
            for (int nt = 0; nt < 4; nt++) {
                int ca0 = 32 * wn + 8 * nt;
                unsigned bb[2][2];
                #pragma unroll
                for (int ks = 0; ks < 2; ks++) {
                    int jc = jb * 64 + ca0 + g;
                    bb[ks][0] = f2t(sk[jc * 17 + 8 * ks + tg]);
                    bb[ks][1] = f2t(sk[jc * 17 + 8 * ks + tg + 4]);
                }
                float sf[4][4];
                #pragma unroll
                for (int mt = 0; mt < 4; mt++)
                    #pragma unroll
                    for (int u = 0; u < 4; u++) sf[mt][u] = 0.f;
                #pragma unroll
                for (int ks = 0; ks < 2; ks++)
                    #pragma unroll
                    for (int mt = 0; mt < 4; mt++)
                        mma8(sf[mt], qf[mt][ks][0], qf[mt][ks][1],
                             qf[mt][ks][2], qf[mt][ks][3],
                             bb[ks][0], bb[ks][1]);
                #pragma unroll
                for (int mt = 0; mt < 4; mt++) {
                    int r0 = 64 * wm + 16 * mt + g;
                    int jg = jb * 64 + ca0 + 2 * tg;   // within-chunk col of c0
                    float s0 = sf[mt][0], s1 = sf[mt][1];
                    float s2 = sf[mt][2], s3 = sf[mt][3];
                    float v0 = (r0 >= jg)     ? fmaf(0.5f * s0, s0, s0 + 1.f) : 0.f;
                    float v1 = (r0 >= jg + 1) ? fmaf(0.5f * s1, s1, s1 + 1.f) : 0.f;
                    float v2 = (r0 + 8 >= jg)     ? fmaf(0.5f * s2, s2, s2 + 1.f) : 0.f;
                    float v3 = (r0 + 8 >= jg + 1) ? fmaf(0.5f * s3, s3, s3 + 1.f) : 0.f;
                    *(uint2*)&sAu[r0 * 68 + ca0 + 2 * tg] =
                        make_uint2(f2t(v0), f2t(v1));
                    *(uint2*)&sAu[(r0 + 8) * 68 + ca0 + 2 * tg] =
                        make_uint2(f2t(v2), f2t(v3));
                    zp[mt][0] += v0 + v1;
                    zp[mt][1] += v2 + v3;
                }
            }
            // z row-sum: reduce over the 4-lane quad, one atomic per row
            #pragma unroll
            for (int mt = 0; mt < 4; mt++)
                #pragma unroll
                for (int h = 0; h < 2; h++) {
                    float v = zp[mt][h];
                    v += __shfl_xor_sync(0xffffffffu, v, 1);
                    v += __shfl_xor_sync(0xffffffffu, v, 2);
                    if (tg == 0)
                        atomicAdd(&szs[64 * wm + 16 * mt + g + 8 * h], v);
                }
        }
        __syncthreads();
        if (wm >= jb) gemm_tile(sAu, sBu, wm, wn, g, tg, c);
        __syncthreads();
    }

    // ---- quadratic inter: A = 0.5*q_d*q_e, B = KVq_prev tile ----
    for (int qb = 0; qb < 4; qb++) {
        for (int i = tid; i < 1024; i += 256) {
            int cc = i >> 4, f4 = (i & 15) * 4;
            float4 v = *(const float4*)&st[OFF_KVQ + qb * 4096 + cc * 64 + f4];
            *(uint4*)&sBu[cc * 72 + f4] =
                make_uint4(f2t(v.x), f2t(v.y), f2t(v.z), f2t(v.w));
        }
        {
            int bd = qb * 4 + 2 * wn;  // d = bd + (cp>>4); e = cp & 15
            #pragma unroll
            for (int rr = 0; rr < 2; rr++) {
                int r = 64 * wm + lane + 32 * rr;
                float qd0 = 0.5f * sq[r * 17 + bd];
                float qd1 = 0.5f * sq[r * 17 + bd + 1];
                float zq = 0.f;
                #pragma unroll
                for (int c4 = 0; c4 < 8; c4++) {
                    unsigned pk[4];
                    #pragma unroll
                    for (int u = 0; u < 4; u++) {
                        int cp = c4 * 4 + u;
                        float val = ((cp < 16) ? qd0 : qd1) * sq[r * 17 + (cp & 15)];
                        zq += val * skk[qb * 64 + 32 * wn + cp];
                        pk[u] = f2t(val);
                    }
                    *(uint4*)&sAu[r * 68 + 32 * wn + c4 * 4] =
                        make_uint4(pk[0], pk[1], pk[2], pk[3]);
                }
                atomicAdd(&szs[r], zq);
            }
        }
        __syncthreads();
        gemm_tile(sAu, sBu, wm, wn, g, tg, c);
        __syncthreads();
    }

    // ---- linear inter: A = Q (reuse qf), B = KVl_prev [16][64] ----
    for (int i = tid; i < 256; i += 256) {
        int cc = i >> 4, f4 = (i & 15) * 4;
        float4 v = *(const float4*)&st[OFF_KVL + cc * 64 + f4];
        *(uint4*)&sBu[cc * 72 + f4] =
            make_uint4(f2t(v.x), f2t(v.y), f2t(v.z), f2t(v.w));
    }
    __syncthreads();
    #pragma unroll
    for (int ks = 0; ks < 2; ks++) {
        unsigned b[4][2];
        #pragma unroll
        for (int nt = 0; nt < 4; nt++) {
            int fc = 32 * wn + 8 * nt + g;
            b[nt][0] = sBu[(8 * ks + tg) * 72 + fc];
            b[nt][1] = sBu[(8 * ks + tg + 4) * 72 + fc];
        }
        #pragma unroll
        for (int mt = 0; mt < 4; mt++)
            #pragma unroll
            for (int nt = 0; nt < 4; nt++)
                mma8(c[mt][nt], qf[mt][ks][0], qf[mt][ks][1],
                     qf[mt][ks][2], qf[mt][ks][3], b[nt][0], b[nt][1]);
    }
    {
        float zl = 0.f;
        #pragma unroll
        for (int kk2 = 0; kk2 < 16; kk2++) zl += sq[tid * 17 + kk2] * sks[kk2];
        szs[tid] += zl;   // all atomics completed before prior barrier
    }
    __syncthreads();

    // ---- epilogue: add vsum_prev, divide by z, store ----
    float* og = out + ((size_t)head * LSEQ + (size_t)ch * CS) * DV;
    #pragma unroll
    for (int mt = 0; mt < 4; mt++) {
        int r0 = 64 * wm + 16 * mt + g;
        float z0 = 1.f / (szs[r0] + 1e-6f);
        float z1 = 1.f / (szs[r0 + 8] + 1e-6f);
        #pragma unroll
        for (int nt = 0; nt < 4; nt++) {
            int f = 32 * wn + 8 * nt + 2 * tg;
            float vs0 = st[OFF_VS + f], vs1 = st[OFF_VS + f + 1];
            *(float2*)&og[r0 * 64 + f] =
                make_float2((c[mt][nt][0] + vs0) * z0, (c[mt][nt][1] + vs1) * z0);
            *(float2*)&og[(r0 + 8) * 64 + f] =
                make_float2((c[mt][nt][2] + vs0) * z1, (c[mt][nt][3] + vs1) * z1);
        }
    }
}

// ---------------------------------------------------------------------------
extern "C" void kernel_launch(void* const* d_in, const int* in_sizes, int n_in,
                              void* d_out, int out_size) {
    const float* q = (const float*)d_in[0];
    const float* k = (const float*)d_in[1];
    const float* v = (const float*)d_in[2];
    float* out = (float*)d_out;

    const int smem1 = (CS * 17 + 256 * 68 + 64 * 72) * (int)sizeof(float);
    const int smem3 = (CS * 17 * 2 + 256 * 68 + 64 * 72 + 256 + 16 + 256) * (int)sizeof(float);

    cudaFuncSetAttribute(k_build, cudaFuncAttributeMaxDynamicSharedMemorySize, smem1);
    cudaFuncSetAttribute(k_main,  cudaFuncAttributeMaxDynamicSharedMemorySize, smem3);

    k_build<<<dim3(BH, NC), 256, smem1>>>(k, v);
    k_scan<<<dim3(BH, 8), 256>>>();
    k_main<<<dim3(BH, NC), 256, smem3>>>(q, k, v, out);
}

// round 4
// speedup vs baseline: 2.2286x; 1.2360x over previous
#include <cuda_runtime.h>
#include <cstdint>

#define BH   32
#define LSEQ 4096
#define DK   16
#define DV   64
#define CS   256
#define NC   16

#define ST_STRIDE 17792
#define OFF_KVQ 0
#define OFF_KVL 16384
#define OFF_KK  17408
#define OFF_KS  17664
#define OFF_VS  17680
#define ST_TOTAL 17744

__device__ float g_state[(size_t)BH * NC * ST_STRIDE];

__device__ __forceinline__ unsigned f2t(float x) {
    unsigned u;
    asm("cvt.rna.tf32.f32 %0, %1;" : "=r"(u) : "f"(x));
    return u;
}
__device__ __forceinline__ float f2tf(float x) { return __uint_as_float(f2t(x)); }
__device__ __forceinline__ unsigned fas(float x) { return __float_as_uint(x); }

__device__ __forceinline__ void mma8(float* c, unsigned a0, unsigned a1,
                                     unsigned a2, unsigned a3,
                                     unsigned b0, unsigned b1) {
    asm volatile(
        "mma.sync.aligned.m16n8k8.row.col.f32.tf32.tf32.f32 "
        "{%0,%1,%2,%3},{%4,%5,%6,%7},{%8,%9},{%0,%1,%2,%3};"
        : "+f"(c[0]), "+f"(c[1]), "+f"(c[2]), "+f"(c[3])
        : "r"(a0), "r"(a1), "r"(a2), "r"(a3), "r"(b0), "r"(b1));
}

// K=64 gemm from staged A (stride 68) + staged B (stride 72); warp rows rb..rb+31
__device__ __forceinline__ void gemm64(const unsigned* __restrict__ sAu,
                                       const unsigned* __restrict__ sBu,
                                       int rb, int wn, int g, int tg,
                                       float c[2][4][4]) {
    #pragma unroll
    for (int ks = 0; ks < 8; ks++) {
        unsigned a[2][4];
        #pragma unroll
        for (int mt = 0; mt < 2; mt++) {
            int rr = rb + 16 * mt + g;
            a[mt][0] = sAu[rr * 68 + 8 * ks + tg];
            a[mt][1] = sAu[(rr + 8) * 68 + 8 * ks + tg];
            a[mt][2] = sAu[rr * 68 + 8 * ks + tg + 4];
            a[mt][3] = sAu[(rr + 8) * 68 + 8 * ks + tg + 4];
        }
        unsigned b[4][2];
        #pragma unroll
        for (int nt = 0; nt < 4; nt++) {
            int fc = 32 * wn + 8 * nt + g;
            b[nt][0] = sBu[(8 * ks + tg) * 72 + fc];
            b[nt][1] = sBu[(8 * ks + tg + 4) * 72 + fc];
        }
        #pragma unroll
        for (int mt = 0; mt < 2; mt++)
            #pragma unroll
            for (int nt = 0; nt < 4; nt++)
                mma8(c[mt][nt], a[mt][0], a[mt][1], a[mt][2], a[mt][3],
                     b[nt][0], b[nt][1]);
    }
}

// ---------------------------------------------------------------------------
// Kernel 1: per-chunk state build. 512 threads, register-built A fragments.
// ---------------------------------------------------------------------------
__global__ __launch_bounds__(512, 1)
void k_build(const float* __restrict__ kin, const float* __restrict__ vin) {
    const int head = blockIdx.x, ch = blockIdx.y;
    extern __shared__ float sm[];
    float* sk = sm;                 // [256][17] tf32-rounded k
    float* sB = sk + CS * 17;       // [64][72]  tf32 V tile
    unsigned* sBu = (unsigned*)sB;

    const float* kg = kin + ((size_t)head * LSEQ + (size_t)ch * CS) * DK;
    const float* vg = vin + ((size_t)head * LSEQ + (size_t)ch * CS) * DV;
    float* st = g_state + (size_t)(head * NC + ch) * ST_STRIDE;

    const int tid = threadIdx.x, warp = tid >> 5, lane = tid & 31;
    const int wm = warp >> 1, wn = warp & 1, g = lane >> 2, tg = lane & 3;

    for (int i = tid; i < CS * DK; i += 512)
        sk[(i >> 4) * 17 + (i & 15)] = f2tf(kg[i]);
    __syncthreads();

    float c[2][4][4];
    #pragma unroll
    for (int mt = 0; mt < 2; mt++)
        #pragma unroll
        for (int nt = 0; nt < 4; nt++)
            #pragma unroll
            for (int u = 0; u < 4; u++) c[mt][nt][u] = 0.f;

    const int kd_d = tid >> 5, kd_f = (tid & 31) * 2;
    float kvl0 = 0.f, kvl1 = 0.f, vsm = 0.f;

    for (int t = 0; t < 4; t++) {
        for (int i = tid; i < 1024; i += 512) {
            int cc = i >> 4, f4 = (i & 15) * 4;
            float4 v = *(const float4*)&vg[(t * 64 + cc) * 64 + f4];
            *(uint4*)&sBu[cc * 72 + f4] =
                make_uint4(f2t(v.x), f2t(v.y), f2t(v.z), f2t(v.w));
        }
        __syncthreads();
        // register-A gemm: A[de][c] = k_d[c]*k_e[c]
        #pragma unroll
        for (int ks = 0; ks < 8; ks++) {
            int c0 = t * 64 + 8 * ks + tg;
            const float* k0 = sk + c0 * 17;
            const float* k1 = k0 + 4 * 17;
            float e00 = k0[g], e01 = k0[g + 8];
            float e10 = k1[g], e11 = k1[g + 8];
            unsigned a[2][4];
            #pragma unroll
            for (int mt = 0; mt < 2; mt++) {
                int d = 2 * wm + mt;
                float kd0 = k0[d], kd1 = k1[d];
                a[mt][0] = fas(kd0 * e00);
                a[mt][1] = fas(kd0 * e01);
                a[mt][2] = fas(kd1 * e10);
                a[mt][3] = fas(kd1 * e11);
            }
            unsigned b[4][2];
            #pragma unroll
            for (int nt = 0; nt < 4; nt++) {
                int fc = 32 * wn + 8 * nt + g;
                b[nt][0] = sBu[(8 * ks + tg) * 72 + fc];
                b[nt][1] = sBu[(8 * ks + tg + 4) * 72 + fc];
            }
            #pragma unroll
            for (int mt = 0; mt < 2; mt++)
                #pragma unroll
                for (int nt = 0; nt < 4; nt++)
                    mma8(c[mt][nt], a[mt][0], a[mt][1], a[mt][2], a[mt][3],
                         b[nt][0], b[nt][1]);
        }
        // kvl / vsum partials from the staged tile
        #pragma unroll 4
        for (int cc = 0; cc < 64; cc++) {
            float kdv = sk[(t * 64 + cc) * 17 + kd_d];
            float2 vv = *(const float2*)&sB[cc * 72 + kd_f];
            kvl0 = fmaf(kdv, vv.x, kvl0);
            kvl1 = fmaf(kdv, vv.y, kvl1);
        }
        if (tid < 64) {
            #pragma unroll 4
            for (int cc = 0; cc < 64; cc++) vsm += sB[cc * 72 + tid];
        }
        __syncthreads();
    }

    #pragma unroll
    for (int mt = 0; mt < 2; mt++)
        #pragma unroll
        for (int nt = 0; nt < 4; nt++) {
            int r0 = 32 * wm + 16 * mt + g, f = 32 * wn + 8 * nt + 2 * tg;
            *(float2*)&st[OFF_KVQ + r0 * 64 + f] =
                make_float2(c[mt][nt][0], c[mt][nt][1]);
            *(float2*)&st[OFF_KVQ + (r0 + 8) * 64 + f] =
                make_float2(c[mt][nt][2], c[mt][nt][3]);
        }
    *(float2*)&st[OFF_KVL + kd_d * 64 + kd_f] = make_float2(kvl0, kvl1);

    {   // kksum: 2 threads per (d,e)
        int pair = tid >> 1, d = pair >> 4, e = pair & 15;
        int cc0 = (tid & 1) * 128;
        float s = 0.f;
        #pragma unroll 4
        for (int cc = cc0; cc < cc0 + 128; cc++)
            s = fmaf(sk[cc * 17 + d], sk[cc * 17 + e], s);
        s += __shfl_xor_sync(0xffffffffu, s, 1);
        if (!(tid & 1)) st[OFF_KK + pair] = s;
    }
    if (tid < DK) {
        float s = 0.f;
        #pragma unroll 4
        for (int cc = 0; cc < CS; cc++) s += sk[cc * 17 + tid];
        st[OFF_KS + tid] = s;
    }
    if (tid < DV) st[OFF_VS + tid] = vsm;
}

// ---------------------------------------------------------------------------
// Kernel 2: exclusive prefix scan over chunk axis.
// ---------------------------------------------------------------------------
__global__ void k_scan() {
    const int head = blockIdx.x;
    float* base = g_state + (size_t)head * NC * ST_STRIDE;
    for (int i = blockIdx.y * blockDim.x + threadIdx.x; i < ST_TOTAL;
         i += gridDim.y * blockDim.x) {
        float run = 0.f;
        #pragma unroll
        for (int c = 0; c < NC; c++) {
            float t = base[(size_t)c * ST_STRIDE + i];
            base[(size_t)c * ST_STRIDE + i] = run;
            run += t;
        }
    }
}

// ---------------------------------------------------------------------------
// Kernel 3: per-(head,chunk) output. 512 threads.
// ---------------------------------------------------------------------------
__global__ __launch_bounds__(512, 1)
void k_main(const float* __restrict__ qin, const float* __restrict__ kin,
            const float* __restrict__ vin, float* __restrict__ out) {
    const int head = blockIdx.x, ch = blockIdx.y;
    extern __shared__ float sm[];
    float* sq  = sm;                 // [256][17] tf32 (scaled q)
    float* sk  = sq + CS * 17;       // [256][17] tf32 k
    float* sA  = sk + CS * 17;       // [256][68] staged phi(S)
    float* sB  = sA + 256 * 68;      // [64][72]
    float* skk = sB + 64 * 72;       // [256]
    float* sks = skk + 256;          // [16]
    float* szs = sks + 16;           // [256]
    unsigned* sAu = (unsigned*)sA;
    unsigned* sBu = (unsigned*)sB;

    const float* qg = qin + ((size_t)head * LSEQ + (size_t)ch * CS) * DK;
    const float* kg = kin + ((size_t)head * LSEQ + (size_t)ch * CS) * DK;
    const float* vg = vin + ((size_t)head * LSEQ + (size_t)ch * CS) * DV;
    const float* st = g_state + (size_t)(head * NC + ch) * ST_STRIDE;

    const int tid = threadIdx.x, warp = tid >> 5, lane = tid & 31;
    const int wm = warp >> 1, wn = warp & 1, g = lane >> 2, tg = lane & 3;
    const int rb = 32 * wm;

    for (int i = tid; i < CS * DK; i += 512) {
        int r = i >> 4, cc = i & 15;
        sq[r * 17 + cc] = f2tf(qg[i] * 0.25f);
        sk[r * 17 + cc] = f2tf(kg[i]);
    }
    if (tid < 256) skk[tid] = st[OFF_KK + tid];
    if (tid < DK) sks[tid] = st[OFF_KS + tid];
    __syncthreads();

    // ---- closed-form z for quadratic + linear inter terms ----
    {
        int row = tid >> 1, dh = (tid & 1) * 8;
        float qr[16];
        #pragma unroll
        for (int d2 = 0; d2 < 16; d2++) qr[d2] = sq[row * 17 + d2];
        float zq = 0.f;
        #pragma unroll
        for (int d2 = dh; d2 < dh + 8; d2++) {
            float inner = 0.f;
            #pragma unroll
            for (int e2 = 0; e2 < 16; e2++)
                inner = fmaf(qr[e2], skk[d2 * 16 + e2], inner);
            zq = fmaf(qr[d2], inner, zq);
        }
        zq += __shfl_xor_sync(0xffffffffu, zq, 1);
        if (!(tid & 1)) {
            float zl = 0.f;
            #pragma unroll
            for (int d2 = 0; d2 < 16; d2++) zl = fmaf(qr[d2], sks[d2], zl);
            szs[row] = (float)(ch * CS) + 0.5f * zq + zl;
        }
    }
    __syncthreads();

    // preload Q fragments
    unsigned qf[2][2][4];
    #pragma unroll
    for (int mt = 0; mt < 2; mt++)
        #pragma unroll
        for (int ks = 0; ks < 2; ks++) {
            int r0 = rb + 16 * mt + g;
            qf[mt][ks][0] = fas(sq[r0 * 17 + 8 * ks + tg]);
            qf[mt][ks][1] = fas(sq[(r0 + 8) * 17 + 8 * ks + tg]);
            qf[mt][ks][2] = fas(sq[r0 * 17 + 8 * ks + tg + 4]);
            qf[mt][ks][3] = fas(sq[(r0 + 8) * 17 + 8 * ks + tg + 4]);
        }

    float c[2][4][4];
    #pragma unroll
    for (int mt = 0; mt < 2; mt++)
        #pragma unroll
        for (int nt = 0; nt < 4; nt++)
            #pragma unroll
            for (int u = 0; u < 4; u++) c[mt][nt][u] = 0.f;

    // ---- intra-chunk: A = mask(1 + S + 0.5 S^2) staged; B = V tile ----
    for (int jb = 0; jb < 4; jb++) {
        for (int i = tid; i < 1024; i += 512) {
            int cc = i >> 4, f4 = (i & 15) * 4;
            float4 v = *(const float4*)&vg[(jb * 64 + cc) * 64 + f4];
            *(uint4*)&sBu[cc * 72 + f4] =
                make_uint4(f2t(v.x), f2t(v.y), f2t(v.z), f2t(v.w));
        }
        if (wm >= 2 * jb) {
            float zp[2][2];
            zp[0][0] = zp[0][1] = zp[1][0] = zp[1][1] = 0.f;
            #pragma unroll
            for (int nt = 0; nt < 4; nt++) {
                int ca0 = 32 * wn + 8 * nt;
                unsigned bb[2][2];
                #pragma unroll
                for (int ks = 0; ks < 2; ks++) {
                    int jc = jb * 64 + ca0 + g;
                    bb[ks][0] = fas(sk[jc * 17 + 8 * ks + tg]);
                    bb[ks][1] = fas(sk[jc * 17 + 8 * ks + tg + 4]);
                }
                float sf[2][4];
                #pragma unroll
                for (int mt = 0; mt < 2; mt++)
                    #pragma unroll
                    for (int u = 0; u < 4; u++) sf[mt][u] = 0.f;
                #pragma unroll
                for (int ks = 0; ks < 2; ks++)
                    #pragma unroll
                    for (int mt = 0; mt < 2; mt++)
                        mma8(sf[mt], qf[mt][ks][0], qf[mt][ks][1],
                             qf[mt][ks][2], qf[mt][ks][3],
                             bb[ks][0], bb[ks][1]);
                #pragma unroll
                for (int mt = 0; mt < 2; mt++) {
                    int r0 = rb + 16 * mt + g;
                    int jg = jb * 64 + ca0 + 2 * tg;
                    float s0 = sf[mt][0], s1 = sf[mt][1];
                    float s2 = sf[mt][2], s3 = sf[mt][3];
                    float v0 = (r0 >= jg)     ? fmaf(0.5f * s0, s0, s0 + 1.f) : 0.f;
                    float v1 = (r0 >= jg + 1) ? fmaf(0.5f * s1, s1, s1 + 1.f) : 0.f;
                    float v2 = (r0 + 8 >= jg)     ? fmaf(0.5f * s2, s2, s2 + 1.f) : 0.f;
                    float v3 = (r0 + 8 >= jg + 1) ? fmaf(0.5f * s3, s3, s3 + 1.f) : 0.f;
                    *(uint2*)&sAu[r0 * 68 + ca0 + 2 * tg] =
                        make_uint2(f2t(v0), f2t(v1));
                    *(uint2*)&sAu[(r0 + 8) * 68 + ca0 + 2 * tg] =
                        make_uint2(f2t(v2), f2t(v3));
                    zp[mt][0] += v0 + v1;
                    zp[mt][1] += v2 + v3;
                }
            }
            #pragma unroll
            for (int mt = 0; mt < 2; mt++)
                #pragma unroll
                for (int h = 0; h < 2; h++) {
                    float v = zp[mt][h];
                    v += __shfl_xor_sync(0xffffffffu, v, 1);
                    v += __shfl_xor_sync(0xffffffffu, v, 2);
                    if (tg == 0)
                        atomicAdd(&szs[rb + 16 * mt + g + 8 * h], v);
                }
        }
        __syncthreads();
        if (wm >= 2 * jb) gemm64(sAu, sBu, rb, wn, g, tg, c);
        __syncthreads();
    }

    // ---- quadratic inter: register A = 0.5*q_d*q_e; B = KVq_prev tile ----
    for (int qb = 0; qb < 4; qb++) {
        for (int i = tid; i < 1024; i += 512) {
            int cc = i >> 4, f4 = (i & 15) * 4;
            float4 v = *(const float4*)&st[OFF_KVQ + qb * 4096 + cc * 64 + f4];
            *(uint4*)&sBu[cc * 72 + f4] =
                make_uint4(f2t(v.x), f2t(v.y), f2t(v.z), f2t(v.w));
        }
        __syncthreads();
        #pragma unroll
        for (int ks = 0; ks < 8; ks++) {
            int c0 = qb * 64 + 8 * ks + tg, c1 = c0 + 4;
            int d0 = (c0 >> 4) & 15, e0 = c0 & 15;
            int d1 = (c1 >> 4) & 15, e1 = c1 & 15;
            unsigned a[2][4];
            #pragma unroll
            for (int mt = 0; mt < 2; mt++) {
                int r = rb + 16 * mt + g;
                const float* q0 = sq + r * 17;
                const float* q1 = q0 + 8 * 17;
                a[mt][0] = fas(0.5f * q0[d0] * q0[e0]);
                a[mt][1] = fas(0.5f * q1[d0] * q1[e0]);
                a[mt][2] = fas(0.5f * q0[d1] * q0[e1]);
                a[mt][3] = fas(0.5f * q1[d1] * q1[e1]);
            }
            unsigned b[4][2];
            #pragma unroll
            for (int nt = 0; nt < 4; nt++) {
                int fc = 32 * wn + 8 * nt + g;
                b[nt][0] = sBu[(8 * ks + tg) * 72 + fc];
                b[nt][1] = sBu[(8 * ks + tg + 4) * 72 + fc];
            }
            #pragma unroll
            for (int mt = 0; mt < 2; mt++)
                #pragma unroll
                for (int nt = 0; nt < 4; nt++)
                    mma8(c[mt][nt], a[mt][0], a[mt][1], a[mt][2], a[mt][3],
                         b[nt][0], b[nt][1]);
        }
        __syncthreads();
    }

    // ---- linear inter: A = Q (qf), B = KVl_prev [16][64] ----
    if (tid < 256) {
        int cc = tid >> 4, f4 = (tid & 15) * 4;
        float4 v = *(const float4*)&st[OFF_KVL + cc * 64 + f4];
        *(uint4*)&sBu[cc * 72 + f4] =
            make_uint4(f2t(v.x), f2t(v.y), f2t(v.z), f2t(v.w));
    }
    __syncthreads();
    #pragma unroll
    for (int ks = 0; ks < 2; ks++) {
        unsigned b[4][2];
        #pragma unroll
        for (int nt = 0; nt < 4; nt++) {
            int fc = 32 * wn + 8 * nt + g;
            b[nt][0] = sBu[(8 * ks + tg) * 72 + fc];
            b[nt][1] = sBu[(8 * ks + tg + 4) * 72 + fc];
        }
        #pragma unroll
        for (int mt = 0; mt < 2; mt++)
            #pragma unroll
            for (int nt = 0; nt < 4; nt++)
                mma8(c[mt][nt], qf[mt][ks][0], qf[mt][ks][1],
                     qf[mt][ks][2], qf[mt][ks][3], b[nt][0], b[nt][1]);
    }
    __syncthreads();

    // ---- epilogue ----
    float* og = out + ((size_t)head * LSEQ + (size_t)ch * CS) * DV;
    #pragma unroll
    for (int mt = 0; mt < 2; mt++) {
        int r0 = rb + 16 * mt + g;
        float z0 = 1.f / (szs[r0] + 1e-6f);
        float z1 = 1.f / (szs[r0 + 8] + 1e-6f);
        #pragma unroll
        for (int nt = 0; nt < 4; nt++) {
            int f = 32 * wn + 8 * nt + 2 * tg;
            float vs0 = st[OFF_VS + f], vs1 = st[OFF_VS + f + 1];
            *(float2*)&og[r0 * 64 + f] =
                make_float2((c[mt][nt][0] + vs0) * z0, (c[mt][nt][1] + vs1) * z0);
            *(float2*)&og[(r0 + 8) * 64 + f] =
                make_float2((c[mt][nt][2] + vs0) * z1, (c[mt][nt][3] + vs1) * z1);
        }
    }
}

// ---------------------------------------------------------------------------
extern "C" void kernel_launch(void* const* d_in, const int* in_sizes, int n_in,
                              void* d_out, int out_size) {
    const float* q = (const float*)d_in[0];
    const float* k = (const float*)d_in[1];
    const float* v = (const float*)d_in[2];
    float* out = (float*)d_out;

    const int smem1 = (CS * 17 + 64 * 72) * (int)sizeof(float);
    const int smem3 = (CS * 17 * 2 + 256 * 68 + 64 * 72 + 256 + 16 + 256) * (int)sizeof(float);

    cudaFuncSetAttribute(k_build, cudaFuncAttributeMaxDynamicSharedMemorySize, smem1);
    cudaFuncSetAttribute(k_main,  cudaFuncAttributeMaxDynamicSharedMemorySize, smem3);

    k_build<<<dim3(BH, NC), 512, smem1>>>(k, v);
    k_scan<<<dim3(BH, 16), 256>>>();
    k_main<<<dim3(BH, NC), 512, smem3>>>(q, k, v, out);
}